// round 2
// baseline (speedup 1.0000x reference)
#include <cuda_runtime.h>

#define NN 100000
#define NE 1600000

// Scratch slots, each NN*64 floats (25.6MB): 0..3
__device__ float g_scratch[4ull * NN * 64];
__device__ float g_deg[NN];
__device__ float g_dinv[NN];
__device__ int g_src[NE];
__device__ int g_dst[NE];
__device__ int g_is64;

// Coefficients of Wm1 slice s in combined matrix A_j (A_j multiplies f_j):
// derived from THETAS for D=2: [[3,-3,0.75],[0,3,-1.5],[0,0,0.75]]
__constant__ float COEF[3][3] = {
    {3.0f,  0.0f,  0.0f},
    {-3.0f, 3.0f,  0.0f},
    {0.75f, -1.5f, 0.75f}
};

__device__ __forceinline__ float* slot(int s) {
    return g_scratch + (size_t)s * (NN * 64);
}

// ---------------------------------------------------------------------------
// Detect whether edge_index buffer is int64 or int32.
// If int64: every 8-byte word has high half == 0 (indices < 2^31).
// If int32: the high half of word i is edge value 2i+1, ~never 0 for 64 words.
__global__ void detect_kernel(const void* ei) {
    if (threadIdx.x == 0 && blockIdx.x == 0) {
        const unsigned long long* p = (const unsigned long long*)ei;
        int is64 = 1;
        for (int i = 0; i < 64; i++) {
            if ((p[i] >> 32) != 0ull) { is64 = 0; break; }
        }
        g_is64 = is64;
    }
}

// Convert edge_index to int32 src/dst arrays, whatever the input dtype.
__global__ void convert_kernel(const void* ei) {
    int e = blockIdx.x * 256 + threadIdx.x;
    if (e < NE) {
        if (g_is64) {
            const long long* p = (const long long*)ei;
            g_src[e] = (int)p[e];
            g_dst[e] = (int)p[NE + e];
        } else {
            const int* p = (const int*)ei;
            g_src[e] = p[e];
            g_dst[e] = p[NE + e];
        }
    }
}

// ---------------------------------------------------------------------------
__global__ void zero_deg_kernel() {
    int i = blockIdx.x * 256 + threadIdx.x;
    if (i < NN) g_deg[i] = 0.0f;
}

__global__ void deg_kernel() {
    int e = blockIdx.x * 256 + threadIdx.x;
    if (e < NE) atomicAdd(&g_deg[g_dst[e]], 1.0f);
}

__global__ void dinv_kernel() {
    int i = blockIdx.x * 256 + threadIdx.x;
    if (i < NN) g_dinv[i] = rsqrtf(fmaxf(g_deg[i], 1.0f));
}

// ---------------------------------------------------------------------------
// Y[N,64] = relu(X[N,K] @ W[K,64] + B), K in {64,128}
// 64-node x 64-col tile per block, 256 threads, 4x4 register blocking.
template <int K>
__global__ __launch_bounds__(256)
void gemm_relu_kernel(const float* __restrict__ Xext, int xslot,
                      const float* __restrict__ W, const float* __restrict__ B,
                      int yslot) {
    const float* X = Xext ? Xext : slot(xslot);
    float* Y = slot(yslot);

    __shared__ float xs[64 * 68];  // transposed: xs[k][node], stride 68
    __shared__ float ws[64 * 64];  // ws[k][col]

    int tid = threadIdx.x;
    int tx = tid & 15, ty = tid >> 4;
    int nodeBase = blockIdx.x * 64;

    float acc[4][4];
#pragma unroll
    for (int i = 0; i < 4; i++)
#pragma unroll
        for (int j = 0; j < 4; j++) acc[i][j] = 0.0f;

    for (int kc = 0; kc < K; kc += 64) {
#pragma unroll
        for (int i = 0; i < 4; i++) {
            int p = i * 256 + tid;     // 0..1023
            int r = p >> 4;            // node row 0..63
            int c4 = p & 15;           // float4 col within chunk
            int node = nodeBase + r;
            float4 v = make_float4(0.f, 0.f, 0.f, 0.f);
            if (node < NN)
                v = *(const float4*)(X + (size_t)node * K + kc + c4 * 4);
            int k0 = c4 * 4;
            xs[(k0 + 0) * 68 + r] = v.x;
            xs[(k0 + 1) * 68 + r] = v.y;
            xs[(k0 + 2) * 68 + r] = v.z;
            xs[(k0 + 3) * 68 + r] = v.w;
        }
#pragma unroll
        for (int i = 0; i < 4; i++) {
            int p = i * 256 + tid;     // p = k*16 + c4
            ((float4*)ws)[p] =
                *(const float4*)(W + (size_t)(kc + (p >> 4)) * 64 + (p & 15) * 4);
        }
        __syncthreads();
#pragma unroll
        for (int k = 0; k < 64; k++) {
            float4 a = *(float4*)&xs[k * 68 + ty * 4];
            float4 b = *(float4*)&ws[k * 64 + tx * 4];
            acc[0][0] += a.x * b.x; acc[0][1] += a.x * b.y; acc[0][2] += a.x * b.z; acc[0][3] += a.x * b.w;
            acc[1][0] += a.y * b.x; acc[1][1] += a.y * b.y; acc[1][2] += a.y * b.z; acc[1][3] += a.y * b.w;
            acc[2][0] += a.z * b.x; acc[2][1] += a.z * b.y; acc[2][2] += a.z * b.z; acc[2][3] += a.z * b.w;
            acc[3][0] += a.w * b.x; acc[3][1] += a.w * b.y; acc[3][2] += a.w * b.z; acc[3][3] += a.w * b.w;
        }
        __syncthreads();
    }

    float4 bb = *(const float4*)&B[tx * 4];
#pragma unroll
    for (int i = 0; i < 4; i++) {
        int node = nodeBase + ty * 4 + i;
        if (node < NN) {
            float4 o;
            o.x = fmaxf(acc[i][0] + bb.x, 0.0f);
            o.y = fmaxf(acc[i][1] + bb.y, 0.0f);
            o.z = fmaxf(acc[i][2] + bb.z, 0.0f);
            o.w = fmaxf(acc[i][3] + bb.w, 0.0f);
            *(float4*)(Y + (size_t)node * 64 + tx * 4) = o;
        }
    }
}

// ---------------------------------------------------------------------------
// g = f * dinv ; msg = 0   (per float4 element)
__global__ __launch_bounds__(256)
void prep_kernel(int fslot, int gslot, int mslot) {
    int i = blockIdx.x * 256 + threadIdx.x;
    if (i < NN * 16) {
        const float4* f = (const float4*)slot(fslot);
        float4* g = (float4*)slot(gslot);
        float4* m = (float4*)slot(mslot);
        float di = g_dinv[i >> 4];
        float4 v = f[i];
        g[i] = make_float4(v.x * di, v.y * di, v.z * di, v.w * di);
        m[i] = make_float4(0.f, 0.f, 0.f, 0.f);
    }
}

// f1 = f0 - msg*dinv ; g = f1*dinv ; msg = 0
__global__ __launch_bounds__(256)
void update_kernel(int f0slot, int msgslot, int f1slot, int gslot) {
    int i = blockIdx.x * 256 + threadIdx.x;
    if (i < NN * 16) {
        const float4* f0 = (const float4*)slot(f0slot);
        float4* msg = (float4*)slot(msgslot);
        float4* f1 = (float4*)slot(f1slot);
        float4* g = (float4*)slot(gslot);
        float di = g_dinv[i >> 4];
        float4 a = f0[i], m = msg[i];
        float4 f;
        f.x = a.x - m.x * di;
        f.y = a.y - m.y * di;
        f.z = a.z - m.z * di;
        f.w = a.w - m.w * di;
        f1[i] = f;
        g[i] = make_float4(f.x * di, f.y * di, f.z * di, f.w * di);
        msg[i] = make_float4(0.f, 0.f, 0.f, 0.f);
    }
}

// ---------------------------------------------------------------------------
// msg[dst] += g[src] over all edges. 16 lanes per edge, float4 per lane.
__global__ __launch_bounds__(256)
void scatter_kernel(int gslot, int mslot) {
    const float4* g = (const float4*)slot(gslot);
    float4* msg = (float4*)slot(mslot);

    int t = blockIdx.x * 256 + threadIdx.x;
    int e = t >> 4;              // grid is sized exactly: e < NE always
    int lane = threadIdx.x & 15;

    int s = g_src[e];
    int d = g_dst[e];

    float4 v = g[(size_t)s * 16 + lane];
#if defined(__CUDA_ARCH__) && (__CUDA_ARCH__ >= 900)
    atomicAdd(&msg[(size_t)d * 16 + lane], v);
#else
    float* mp = (float*)&msg[(size_t)d * 16 + lane];
    atomicAdd(mp + 0, v.x);
    atomicAdd(mp + 1, v.y);
    atomicAdd(mp + 2, v.z);
    atomicAdd(mp + 3, v.w);
#endif
}

// ---------------------------------------------------------------------------
// Final: f2 = f1 - msg*dinv (on the fly); hf = relu(sum_j f_j @ A_j + bm1);
// out = hf @ Wm2 + bm2. A_j built per block from Wm1 slices via COEF.
__global__ __launch_bounds__(256)
void final_kernel(int f0slot, int f1slot, int msgslot,
                  const float* __restrict__ Wm1, const float* __restrict__ bm1,
                  const float* __restrict__ Wm2, const float* __restrict__ bm2,
                  float* __restrict__ out) {
    const float4* f0 = (const float4*)slot(f0slot);
    const float4* f1 = (const float4*)slot(f1slot);
    const float4* msg = (const float4*)slot(msgslot);

    __shared__ float fs[64 * 68];  // transposed f tile, later reused as hf[node][col]
    __shared__ float as[64 * 64];  // A_j[k][col]
    __shared__ float wm2s[128];

    int tid = threadIdx.x;
    int tx = tid & 15, ty = tid >> 4;
    int nodeBase = blockIdx.x * 64;

    if (tid < 128) wm2s[tid] = Wm2[tid];

    float acc[4][4];
#pragma unroll
    for (int i = 0; i < 4; i++)
#pragma unroll
        for (int j = 0; j < 4; j++) acc[i][j] = 0.0f;

    const float4* Wm1_4 = (const float4*)Wm1;

    for (int j = 0; j < 3; j++) {
        float c0 = COEF[j][0], c1 = COEF[j][1], c2 = COEF[j][2];
        // build A_j (64x64) in smem
#pragma unroll
        for (int i = 0; i < 4; i++) {
            int p = i * 256 + tid;  // p = k*16 + c4
            float4 w0 = Wm1_4[p];
            float4 w1 = Wm1_4[1024 + p];
            float4 w2 = Wm1_4[2048 + p];
            float4 a;
            a.x = c0 * w0.x + c1 * w1.x + c2 * w2.x;
            a.y = c0 * w0.y + c1 * w1.y + c2 * w2.y;
            a.z = c0 * w0.z + c1 * w1.z + c2 * w2.z;
            a.w = c0 * w0.w + c1 * w1.w + c2 * w2.w;
            ((float4*)as)[p] = a;
        }
        // load f_j tile transposed into fs
#pragma unroll
        for (int i = 0; i < 4; i++) {
            int p = i * 256 + tid;
            int r = p >> 4, c4 = p & 15;
            int node = nodeBase + r;
            float4 v = make_float4(0.f, 0.f, 0.f, 0.f);
            if (node < NN) {
                int idx = node * 16 + c4;
                if (j == 0) {
                    v = f0[idx];
                } else if (j == 1) {
                    v = f1[idx];
                } else {
                    float4 a1 = f1[idx], m = msg[idx];
                    float di = g_dinv[node];
                    v.x = a1.x - m.x * di;
                    v.y = a1.y - m.y * di;
                    v.z = a1.z - m.z * di;
                    v.w = a1.w - m.w * di;
                }
            }
            int k0 = c4 * 4;
            fs[(k0 + 0) * 68 + r] = v.x;
            fs[(k0 + 1) * 68 + r] = v.y;
            fs[(k0 + 2) * 68 + r] = v.z;
            fs[(k0 + 3) * 68 + r] = v.w;
        }
        __syncthreads();
#pragma unroll
        for (int k = 0; k < 64; k++) {
            float4 a = *(float4*)&fs[k * 68 + ty * 4];
            float4 b = *(float4*)&as[k * 64 + tx * 4];
            acc[0][0] += a.x * b.x; acc[0][1] += a.x * b.y; acc[0][2] += a.x * b.z; acc[0][3] += a.x * b.w;
            acc[1][0] += a.y * b.x; acc[1][1] += a.y * b.y; acc[1][2] += a.y * b.z; acc[1][3] += a.y * b.w;
            acc[2][0] += a.z * b.x; acc[2][1] += a.z * b.y; acc[2][2] += a.z * b.z; acc[2][3] += a.z * b.w;
            acc[3][0] += a.w * b.x; acc[3][1] += a.w * b.y; acc[3][2] += a.w * b.z; acc[3][3] += a.w * b.w;
        }
        __syncthreads();
    }

    // bias + relu -> store hf into fs as [node][col], stride 68
    float4 bb = *(const float4*)&bm1[tx * 4];
#pragma unroll
    for (int i = 0; i < 4; i++) {
        int r = ty * 4 + i;
        float4 o;
        o.x = fmaxf(acc[i][0] + bb.x, 0.0f);
        o.y = fmaxf(acc[i][1] + bb.y, 0.0f);
        o.z = fmaxf(acc[i][2] + bb.z, 0.0f);
        o.w = fmaxf(acc[i][3] + bb.w, 0.0f);
        *(float4*)&fs[r * 68 + tx * 4] = o;
    }
    __syncthreads();

    // out[n][c] = bm2[c] + sum_k hf[n][k] * Wm2[k][c]
    if (tid < 128) {
        int n = tid >> 1, c = tid & 1;
        int node = nodeBase + n;
        if (node < NN) {
            float s = bm2[c];
#pragma unroll
            for (int k = 0; k < 64; k++) s += fs[n * 68 + k] * wm2s[k * 2 + c];
            out[(size_t)node * 2 + c] = s;
        }
    }
}

// ---------------------------------------------------------------------------
extern "C" void kernel_launch(void* const* d_in, const int* in_sizes, int n_in,
                              void* d_out, int out_size) {
    const float* x = (const float*)d_in[0];
    const void* ei = d_in[1];
    const float* W1 = (const float*)d_in[2];
    const float* b1 = (const float*)d_in[3];
    const float* W2 = (const float*)d_in[4];
    const float* b2 = (const float*)d_in[5];
    const float* Wm1 = (const float*)d_in[6];
    const float* bm1 = (const float*)d_in[7];
    const float* Wm2 = (const float*)d_in[8];
    const float* bm2 = (const float*)d_in[9];
    float* out = (float*)d_out;

    // dtype-agnostic edge index materialization (int32 arrays)
    detect_kernel<<<1, 32>>>(ei);
    convert_kernel<<<(NE + 255) / 256, 256>>>(ei);

    // degrees -> dinv
    zero_deg_kernel<<<(NN + 255) / 256, 256>>>();
    deg_kernel<<<(NE + 255) / 256, 256>>>();
    dinv_kernel<<<(NN + 255) / 256, 256>>>();

    int nb = (NN + 63) / 64;  // 1563
    // h1 = relu(x @ W1 + b1)          -> slot 0
    gemm_relu_kernel<128><<<nb, 256>>>(x, -1, W1, b1, 0);
    // f0 = relu(h1 @ W2 + b2)         -> slot 1
    gemm_relu_kernel<64><<<nb, 256>>>(nullptr, 0, W2, b2, 1);

    int nv = (NN * 16 + 255) / 256;
    int ns = (NE * 16) / 256;  // exact: 100000 blocks

    // pass 1: g(slot2) = f0*dinv, msg(slot3)=0; msg += g[src]
    prep_kernel<<<nv, 256>>>(1, 2, 3);
    scatter_kernel<<<ns, 256>>>(2, 3);
    // f1(slot0) = f0 - msg*dinv ; g(slot2)=f1*dinv ; msg(slot3)=0
    update_kernel<<<nv, 256>>>(1, 3, 0, 2);
    // pass 2
    scatter_kernel<<<ns, 256>>>(2, 3);

    // final fused MLP (f2 computed on the fly from f1, msg)
    final_kernel<<<nb, 256>>>(1, 0, 3, Wm1, bm1, Wm2, bm2, out);
}